// round 2
// baseline (speedup 1.0000x reference)
#include <cuda_runtime.h>

#define Bsz 512
#define Tsz 256
#define Fsz 256
#define Hsz 512

// Ping-pong hidden state + cell state scratch (no allocation allowed).
__device__ float d_hbuf[2][Bsz * Hsz];
__device__ float d_c[Bsz * Hsz];

__global__ void init_state_kernel() {
    int i = blockIdx.x * blockDim.x + threadIdx.x;
    if (i < Bsz * Hsz) {
        d_hbuf[0][i] = 0.f;
        d_c[i] = 0.f;
    }
}

// One LSTM time step, fully fused:
//   gates[b, g*512+n] = sum_k h[b,k]*W_hh[g*512+n,k] + sum_f x[b,t,f]*W_ih[g*512+n,f] + b_ih + b_hh
// then pointwise cell update. Grid: (512/64) x (512/32) = 128 blocks, 256 threads.
// Thread micro-tile: 4 batch x 2 hidden x 4 gates = 32 accumulators.
__global__ __launch_bounds__(256, 1)
void lstm_step_kernel(const float* __restrict__ x,
                      const float* __restrict__ Wih,
                      const float* __restrict__ Whh,
                      const float* __restrict__ bih,
                      const float* __restrict__ bhh,
                      int t)
{
    __shared__ __align__(16) float Hs[16][64];      // [k][b]
    __shared__ __align__(16) float Ws[4][16][32];   // [gate][k][n]

    const int tid = threadIdx.x;
    const int tx = tid & 15;   // hidden pairs: n = n0 + tx*2 + {0,1}
    const int ty = tid >> 4;   // batch quads:  b = b0 + ty*4 + {0..3}
    const int b0 = blockIdx.x * 64;
    const int n0 = blockIdx.y * 32;

    const float* __restrict__ hin  = d_hbuf[t & 1];
    float* __restrict__       hout = d_hbuf[(t + 1) & 1];

    float acc[4][4][2];  // [bi][gate][ni]
    #pragma unroll
    for (int bi = 0; bi < 4; bi++)
        #pragma unroll
        for (int g = 0; g < 4; g++) {
            acc[bi][g][0] = 0.f;
            acc[bi][g][1] = 0.f;
        }

    const int lrow = tid >> 2;        // 0..63 (batch row for Hs load)
    const int lk   = (tid & 3) * 4;   // 0,4,8,12

    // K loop over [h (512) | x_t (256)] = 768, BK = 16 -> 48 chunks
    for (int k0 = 0; k0 < Hsz + Fsz; k0 += 16) {
        // ---- global loads into registers ----
        float4 hv;
        if (k0 < Hsz)
            hv = *(const float4*)(hin + (size_t)(b0 + lrow) * Hsz + k0 + lk);
        else
            hv = *(const float4*)(x + ((size_t)(b0 + lrow) * Tsz + t) * Fsz + (k0 - Hsz) + lk);

        float4 wv[2];
        int wg[2], wn[2], wkk[2];
        #pragma unroll
        for (int j = 0; j < 2; j++) {
            int q = tid + j * 256;     // float4 index 0..511
            int r = q >> 2;            // weight row 0..127 within tile
            wg[j]  = r >> 5;           // gate 0..3
            wn[j]  = r & 31;           // hidden col 0..31
            wkk[j] = (q & 3) * 4;      // k sub-offset 0,4,8,12
            int n4 = wg[j] * Hsz + n0 + wn[j];
            if (k0 < Hsz)
                wv[j] = *(const float4*)(Whh + (size_t)n4 * Hsz + k0 + wkk[j]);
            else
                wv[j] = *(const float4*)(Wih + (size_t)n4 * Fsz + (k0 - Hsz) + wkk[j]);
        }

        // ---- stage into shared ----
        Hs[lk + 0][lrow] = hv.x;
        Hs[lk + 1][lrow] = hv.y;
        Hs[lk + 2][lrow] = hv.z;
        Hs[lk + 3][lrow] = hv.w;
        #pragma unroll
        for (int j = 0; j < 2; j++) {
            Ws[wg[j]][wkk[j] + 0][wn[j]] = wv[j].x;
            Ws[wg[j]][wkk[j] + 1][wn[j]] = wv[j].y;
            Ws[wg[j]][wkk[j] + 2][wn[j]] = wv[j].z;
            Ws[wg[j]][wkk[j] + 3][wn[j]] = wv[j].w;
        }
        __syncthreads();

        // ---- FMA core ----
        #pragma unroll
        for (int kk = 0; kk < 16; kk++) {
            float4 a = *(const float4*)&Hs[kk][ty * 4];
            float av[4] = {a.x, a.y, a.z, a.w};
            float2 w0 = *(const float2*)&Ws[0][kk][tx * 2];
            float2 w1 = *(const float2*)&Ws[1][kk][tx * 2];
            float2 w2 = *(const float2*)&Ws[2][kk][tx * 2];
            float2 w3 = *(const float2*)&Ws[3][kk][tx * 2];
            #pragma unroll
            for (int bi = 0; bi < 4; bi++) {
                acc[bi][0][0] += av[bi] * w0.x;  acc[bi][0][1] += av[bi] * w0.y;
                acc[bi][1][0] += av[bi] * w1.x;  acc[bi][1][1] += av[bi] * w1.y;
                acc[bi][2][0] += av[bi] * w2.x;  acc[bi][2][1] += av[bi] * w2.y;
                acc[bi][3][0] += av[bi] * w3.x;  acc[bi][3][1] += av[bi] * w3.y;
            }
        }
        __syncthreads();
    }

    // ---- epilogue: bias + activations + state update ----
    #pragma unroll
    for (int ni = 0; ni < 2; ni++) {
        int n = n0 + tx * 2 + ni;
        float bI = bih[n]        + bhh[n];
        float bF = bih[n +  512] + bhh[n +  512];
        float bG = bih[n + 1024] + bhh[n + 1024];
        float bO = bih[n + 1536] + bhh[n + 1536];
        #pragma unroll
        for (int bi = 0; bi < 4; bi++) {
            int b = b0 + ty * 4 + bi;
            float gi = acc[bi][0][ni] + bI;
            float gf = acc[bi][1][ni] + bF;
            float gg = acc[bi][2][ni] + bG;
            float go = acc[bi][3][ni] + bO;
            float iv = 1.f / (1.f + expf(-gi));
            float fv = 1.f / (1.f + expf(-gf));
            float gv = tanhf(gg);
            float ov = 1.f / (1.f + expf(-go));
            int idx = b * Hsz + n;
            float cn = fv * d_c[idx] + iv * gv;
            d_c[idx] = cn;
            hout[idx] = ov * tanhf(cn);
        }
    }
}

// out[b] = h_final[b,:] . W_out[0,:] + b_out[0]; one warp per batch row.
__global__ void head_kernel(const float* __restrict__ Wout,
                            const float* __restrict__ bout,
                            float* __restrict__ out)
{
    int w    = (blockIdx.x * blockDim.x + threadIdx.x) >> 5;
    int lane = threadIdx.x & 31;
    if (w >= Bsz) return;
    const float* hr = d_hbuf[0] + (size_t)w * Hsz;  // t=255 writes buf 0
    float s = 0.f;
    for (int k = lane; k < Hsz; k += 32) s += hr[k] * Wout[k];
    #pragma unroll
    for (int o = 16; o > 0; o >>= 1) s += __shfl_xor_sync(0xffffffffu, s, o);
    if (lane == 0) out[w] = s + bout[0];
}

extern "C" void kernel_launch(void* const* d_in, const int* in_sizes, int n_in,
                              void* d_out, int out_size)
{
    const float* x    = (const float*)d_in[0];
    const float* Wih  = (const float*)d_in[1];
    const float* Whh  = (const float*)d_in[2];
    const float* bih  = (const float*)d_in[3];
    const float* bhh  = (const float*)d_in[4];
    const float* Wout = (const float*)d_in[5];
    const float* bout = (const float*)d_in[6];
    float* out = (float*)d_out;
    (void)in_sizes; (void)n_in; (void)out_size;

    init_state_kernel<<<(Bsz * Hsz + 255) / 256, 256>>>();

    dim3 grid(Bsz / 64, Hsz / 32);  // 8 x 16 = 128 blocks
    for (int t = 0; t < Tsz; t++)
        lstm_step_kernel<<<grid, 256>>>(x, Wih, Whh, bih, bhh, t);

    head_kernel<<<64, 256>>>(Wout, bout, out);
}

// round 6
// speedup vs baseline: 1.9126x; 1.9126x over previous
#include <cuda_runtime.h>
#include <cuda_bf16.h>
#include <mma.h>
#include <cstdint>

using namespace nvcuda;

#define Bsz 512
#define Tsz 256
#define Fsz 256
#define Hsz 512
#define KTOT 768            // [h (512) | x_t (256)]
#define NG   2048           // 4H packed gate rows, reordered r = u*4 + gate

#define TM 64               // CTA batch tile
#define TN 128              // CTA packed-gate tile
#define TK 32               // K chunk
#define LDA 40              // padded ld (bf16 elems) for A/W tiles
#define LDG 132             // padded ld (f32 elems) for gate buffer

// stage layout (byte offsets within one stage)
#define A_HI_OFF 0
#define A_LO_OFF (TM * LDA * 2)                       // 5120
#define W_HI_OFF (2 * TM * LDA * 2)                   // 10240
#define W_LO_OFF (2 * TM * LDA * 2 + TN * LDA * 2)    // 20480
#define STAGE_B  (2 * TM * LDA * 2 + 2 * TN * LDA * 2) // 30720
#define SMEM_BYTES (2 * STAGE_B)                      // 61440 (gate buf aliases)

// ---------------- device scratch (no allocation allowed) ----------------
__device__ __nv_bfloat16 d_xhi[(size_t)Bsz * Tsz * Fsz];
__device__ __nv_bfloat16 d_xlo[(size_t)Bsz * Tsz * Fsz];
__device__ __nv_bfloat16 d_whi[NG * KTOT];
__device__ __nv_bfloat16 d_wlo[NG * KTOT];
__device__ float         d_bias[NG];
__device__ __nv_bfloat16 d_hhi[2][Bsz * Hsz];
__device__ __nv_bfloat16 d_hlo[2][Bsz * Hsz];
__device__ float         d_c[Bsz * Hsz];

// ---------------- helpers ----------------
__device__ __forceinline__ uint32_t smem_u32(const void* p) {
    uint32_t a;
    asm("{ .reg .u64 t; cvta.to.shared.u64 t, %1; cvt.u32.u64 %0, t; }" : "=r"(a) : "l"(p));
    return a;
}
#define CP16(smaddr, gptr) \
    asm volatile("cp.async.cg.shared.global [%0], [%1], 16;" :: "r"(smaddr), "l"(gptr) : "memory")
#define CP_COMMIT() asm volatile("cp.async.commit_group;" ::: "memory")
#define CP_WAIT(n)  asm volatile("cp.async.wait_group %0;" :: "n"(n) : "memory")

// ---------------- prep kernels ----------------
__global__ void prep_x_kernel(const float* __restrict__ x) {
    size_t i = (size_t)blockIdx.x * blockDim.x + threadIdx.x;
    if (i < (size_t)Bsz * Tsz * Fsz) {
        float v = x[i];
        __nv_bfloat16 hi = __float2bfloat16(v);
        d_xhi[i] = hi;
        d_xlo[i] = __float2bfloat16(v - __bfloat162float(hi));
    }
}

__global__ void prep_w_kernel(const float* __restrict__ Wih, const float* __restrict__ Whh) {
    size_t i = (size_t)blockIdx.x * blockDim.x + threadIdx.x;
    if (i < (size_t)NG * KTOT) {
        int r = (int)(i / KTOT), kc = (int)(i % KTOT);
        int u = r >> 2, g = r & 3;
        int orow = g * Hsz + u;
        float v = (kc < Hsz) ? Whh[(size_t)orow * Hsz + kc]
                             : Wih[(size_t)orow * Fsz + (kc - Hsz)];
        __nv_bfloat16 hi = __float2bfloat16(v);
        d_whi[i] = hi;
        d_wlo[i] = __float2bfloat16(v - __bfloat162float(hi));
    }
}

__global__ void prep_bias_kernel(const float* __restrict__ bih, const float* __restrict__ bhh) {
    int r = blockIdx.x * blockDim.x + threadIdx.x;
    if (r < NG) {
        int u = r >> 2, g = r & 3;
        d_bias[r] = bih[g * Hsz + u] + bhh[g * Hsz + u];
    }
}

__global__ void init_state_kernel() {
    int i = blockIdx.x * blockDim.x + threadIdx.x;
    if (i < Bsz * Hsz) {
        __nv_bfloat16 z = __float2bfloat16(0.f);
        d_hhi[0][i] = z; d_hhi[1][i] = z;
        d_hlo[0][i] = z; d_hlo[1][i] = z;
        d_c[i] = 0.f;
    }
}

// ---------------- fused wmma LSTM step ----------------
// Grid (8, 16): batch tiles (M=64) x packed-gate tiles (N=128 = 32 units x 4 gates).
// 8 warps: warp (wm, wn) owns a 32x32 output tile = 2x2 wmma 16x16x16 fragments.
// Split-bf16: acc += Ahi*Whi + Ahi*Wlo + Alo*Whi  (fp32 accumulate).
__global__ __launch_bounds__(256, 1)
void lstm_step_mma(int t)
{
    extern __shared__ __align__(16) char smem[];
    const int tid = threadIdx.x;
    const int wid = tid >> 5;
    const int b0 = blockIdx.x * TM;
    const int n0 = blockIdx.y * TN;
    const int wm = wid & 1;          // 0..1: rows wm*32
    const int wn = wid >> 1;         // 0..3: cols wn*32

    const __nv_bfloat16* __restrict__ hin_hi = d_hhi[t & 1];
    const __nv_bfloat16* __restrict__ hin_lo = d_hlo[t & 1];

    wmma::fragment<wmma::accumulator, 16, 16, 16, float> acc[2][2];
    #pragma unroll
    for (int mi = 0; mi < 2; mi++)
        #pragma unroll
        for (int ni = 0; ni < 2; ni++)
            wmma::fill_fragment(acc[mi][ni], 0.f);

    // per-thread load assignments (constant across chunks)
    const int ar = tid >> 2, as = tid & 3;        // A: row 0..63, seg 0..3 (8 bf16 each)

    // issue cp.async loads for chunk c into stage buffer stg
    auto issue = [&](int c, char* stg) {
        int k0 = c * TK;
        const __nv_bfloat16 *ahi, *alo;
        if (c < 16) {
            size_t off = (size_t)(b0 + ar) * Hsz + k0 + as * 8;
            ahi = hin_hi + off; alo = hin_lo + off;
        } else {
            size_t off = ((size_t)(b0 + ar) * Tsz + t) * Fsz + (k0 - Hsz) + as * 8;
            ahi = d_xhi + off; alo = d_xlo + off;
        }
        uint32_t sa = smem_u32(stg) + (uint32_t)(ar * LDA + as * 8) * 2;
        CP16(sa + A_HI_OFF, ahi);
        CP16(sa + A_LO_OFF, alo);
        #pragma unroll
        for (int j = 0; j < 2; j++) {
            int idx = tid + j * 256;              // 512 segs: row 0..127, seg 0..3
            int wr = idx >> 2, ws = idx & 3;
            size_t goff = (size_t)(n0 + wr) * KTOT + k0 + ws * 8;
            uint32_t sw = smem_u32(stg) + (uint32_t)(wr * LDA + ws * 8) * 2;
            CP16(sw + W_HI_OFF, d_whi + goff);
            CP16(sw + W_LO_OFF, d_wlo + goff);
        }
        CP_COMMIT();
    };

    char* stg0 = smem;
    char* stg1 = smem + STAGE_B;

    issue(0, stg0);

    #pragma unroll 1
    for (int c = 0; c < 24; c++) {
        char* stg = (c & 1) ? stg1 : stg0;
        if (c + 1 < 24) {
            issue(c + 1, (c & 1) ? stg0 : stg1);
            CP_WAIT(1);                            // chunk c resident
        } else {
            CP_WAIT(0);
        }
        __syncthreads();

        const __nv_bfloat16* As_hi = (const __nv_bfloat16*)(stg + A_HI_OFF);
        const __nv_bfloat16* As_lo = (const __nv_bfloat16*)(stg + A_LO_OFF);
        const __nv_bfloat16* Ws_hi = (const __nv_bfloat16*)(stg + W_HI_OFF);
        const __nv_bfloat16* Ws_lo = (const __nv_bfloat16*)(stg + W_LO_OFF);

        #pragma unroll
        for (int kk = 0; kk < TK; kk += 16) {
            wmma::fragment<wmma::matrix_a, 16, 16, 16, __nv_bfloat16, wmma::row_major> ahi[2], alo[2];
            wmma::fragment<wmma::matrix_b, 16, 16, 16, __nv_bfloat16, wmma::col_major> bhi[2], blo[2];
            #pragma unroll
            for (int mi = 0; mi < 2; mi++) {
                int r = (wm * 32 + mi * 16) * LDA + kk;
                wmma::load_matrix_sync(ahi[mi], As_hi + r, LDA);
                wmma::load_matrix_sync(alo[mi], As_lo + r, LDA);
            }
            #pragma unroll
            for (int ni = 0; ni < 2; ni++) {
                int r = (wn * 32 + ni * 16) * LDA + kk;
                wmma::load_matrix_sync(bhi[ni], Ws_hi + r, LDA);
                wmma::load_matrix_sync(blo[ni], Ws_lo + r, LDA);
            }
            #pragma unroll
            for (int mi = 0; mi < 2; mi++)
                #pragma unroll
                for (int ni = 0; ni < 2; ni++) {
                    wmma::mma_sync(acc[mi][ni], ahi[mi], bhi[ni], acc[mi][ni]);
                    wmma::mma_sync(acc[mi][ni], ahi[mi], blo[ni], acc[mi][ni]);
                    wmma::mma_sync(acc[mi][ni], alo[mi], bhi[ni], acc[mi][ni]);
                }
        }
        __syncthreads();                           // stage reusable next iter
    }

    // ---- epilogue: gates -> SMEM (aliasing dead stages) -> cell update ----
    float* G = (float*)smem;                       // [TM][LDG] f32 = 33792 B
    #pragma unroll
    for (int mi = 0; mi < 2; mi++)
        #pragma unroll
        for (int ni = 0; ni < 2; ni++)
            wmma::store_matrix_sync(G + (wm * 32 + mi * 16) * LDG + wn * 32 + ni * 16,
                                    acc[mi][ni], LDG, wmma::mem_row_major);
    __syncthreads();

    {
        int row = tid >> 2;                        // 0..63
        int b = b0 + row;
        float* crow = d_c + (size_t)b * Hsz;
        __nv_bfloat16* hh = d_hhi[(t + 1) & 1] + (size_t)b * Hsz;
        __nv_bfloat16* hl = d_hlo[(t + 1) & 1] + (size_t)b * Hsz;
        const int u0 = n0 >> 2;
        #pragma unroll
        for (int j = 0; j < 8; j++) {
            int ul = (tid & 3) + j * 4;            // 0..31
            int col = ul * 4;
            float gi = G[row * LDG + col + 0] + d_bias[n0 + col + 0];
            float gf = G[row * LDG + col + 1] + d_bias[n0 + col + 1];
            float gg = G[row * LDG + col + 2] + d_bias[n0 + col + 2];
            float go = G[row * LDG + col + 3] + d_bias[n0 + col + 3];
            float iv = 1.f / (1.f + __expf(-gi));
            float fv = 1.f / (1.f + __expf(-gf));
            float gv = 2.f / (1.f + __expf(-2.f * gg)) - 1.f;
            float ov = 1.f / (1.f + __expf(-go));
            int u = u0 + ul;
            float cn = fv * crow[u] + iv * gv;
            crow[u] = cn;
            float hn = ov * (2.f / (1.f + __expf(-2.f * cn)) - 1.f);
            __nv_bfloat16 hi = __float2bfloat16(hn);
            hh[u] = hi;
            hl[u] = __float2bfloat16(hn - __bfloat162float(hi));
        }
    }
}

// out[b] = (h_hi+h_lo)[b,:] . W_out[0,:] + b_out[0]
__global__ void head_kernel(const float* __restrict__ Wout,
                            const float* __restrict__ bout,
                            float* __restrict__ out)
{
    int w = (blockIdx.x * blockDim.x + threadIdx.x) >> 5;
    int lane = threadIdx.x & 31;
    if (w >= Bsz) return;
    const __nv_bfloat16* hh = d_hhi[0] + (size_t)w * Hsz;  // T=256 even -> buf 0
    const __nv_bfloat16* hl = d_hlo[0] + (size_t)w * Hsz;
    float s = 0.f;
    for (int k = lane; k < Hsz; k += 32)
        s += (__bfloat162float(hh[k]) + __bfloat162float(hl[k])) * Wout[k];
    #pragma unroll
    for (int o = 16; o > 0; o >>= 1) s += __shfl_xor_sync(0xffffffffu, s, o);
    if (lane == 0) out[w] = s + bout[0];
}

extern "C" void kernel_launch(void* const* d_in, const int* in_sizes, int n_in,
                              void* d_out, int out_size)
{
    const float* x    = (const float*)d_in[0];
    const float* Wih  = (const float*)d_in[1];
    const float* Whh  = (const float*)d_in[2];
    const float* bih  = (const float*)d_in[3];
    const float* bhh  = (const float*)d_in[4];
    const float* Wout = (const float*)d_in[5];
    const float* bout = (const float*)d_in[6];
    float* out = (float*)d_out;
    (void)in_sizes; (void)n_in; (void)out_size;

    cudaFuncSetAttribute(lstm_step_mma, cudaFuncAttributeMaxDynamicSharedMemorySize, SMEM_BYTES);

    size_t nx = (size_t)Bsz * Tsz * Fsz;
    prep_x_kernel<<<(unsigned)((nx + 255) / 256), 256>>>(x);
    prep_w_kernel<<<(NG * KTOT + 255) / 256, 256>>>(Wih, Whh);
    prep_bias_kernel<<<(NG + 255) / 256, 256>>>(bih, bhh);
    init_state_kernel<<<(Bsz * Hsz + 255) / 256, 256>>>();

    dim3 grid(Bsz / TM, NG / TN);   // 8 x 16 = 128 CTAs
    for (int t = 0; t < Tsz; t++)
        lstm_step_mma<<<grid, 256, SMEM_BYTES>>>(t);

    head_kernel<<<64, 256>>>(Wout, bout, out);
}

// round 7
// speedup vs baseline: 2.2688x; 1.1862x over previous
#include <cuda_runtime.h>
#include <cuda_bf16.h>
#include <mma.h>
#include <cstdint>

using namespace nvcuda;

#define Bsz 512
#define Tsz 256
#define Fsz 256
#define Hsz 512
#define NG  2048            // 4H packed gate rows, r = u*4 + gate
#define NCTA 128            // persistent grid (4 x 32)

// ---- persistent step kernel tiles ----
#define TM 128              // batch tile
#define TN 64               // packed-gate tile (= 16 units)
#define TK 64               // K chunk of the h-GEMM (K=512 -> 8 chunks)
#define LDA_S 72            // A stage ld (bf16)
#define LDW  520            // resident W ld (bf16)
#define LDG_S 68            // gate stage ld (f32)

// step-kernel SMEM layout (bytes)
#define WHI_OFF   0                       // 64 x 520 bf16 = 66560
#define WLO_OFF   66560
#define STAGE0_OFF 133120                 // 2 stages x 36864
#define STAGE_SZ  36864
#define AHI_OFF   0                       // 128 x 72 bf16 = 18432
#define ALO_OFF   18432
#define CT_OFF    206848                  // c tile 128 x 16 f32 = 8192
#define SMEM_STEP 215040
// G (f32 gate stage, 128 x 68 x 4 = 34816) aliases STAGE0 region

// ---- xproj kernel tiles ----
#define XTK 64
#define XSTAGE_SZ 73728                   // A hi/lo + W hi/lo, 128x72 bf16 each
#define XAHI 0
#define XALO 18432
#define XWHI 36864
#define XWLO 55296
#define SMEM_XPROJ 147456

// ---------------- device scratch (no runtime allocation) ----------------
__device__ __nv_bfloat16 d_xhi[(size_t)Bsz * Tsz * Fsz];
__device__ __nv_bfloat16 d_xlo[(size_t)Bsz * Tsz * Fsz];
__device__ __nv_bfloat16 d_whh_hi[NG * Hsz];
__device__ __nv_bfloat16 d_whh_lo[NG * Hsz];
__device__ __nv_bfloat16 d_wih_hi[NG * Fsz];
__device__ __nv_bfloat16 d_wih_lo[NG * Fsz];
__device__ float         d_bias[NG];
__device__ __nv_bfloat16 d_hhi[2][Bsz * Hsz];
__device__ __nv_bfloat16 d_hlo[2][Bsz * Hsz];
__device__ float         d_gx[(size_t)Bsz * Tsz * NG];   // precomputed x-projection
__device__ unsigned          d_bar_cnt;
__device__ volatile unsigned d_bar_gen;

// ---------------- helpers ----------------
__device__ __forceinline__ uint32_t smem_u32(const void* p) {
    uint32_t a;
    asm("{ .reg .u64 t; cvta.to.shared.u64 t, %1; cvt.u32.u64 %0, t; }" : "=r"(a) : "l"(p));
    return a;
}
#define CP16(smaddr, gptr) \
    asm volatile("cp.async.cg.shared.global [%0], [%1], 16;" :: "r"(smaddr), "l"(gptr) : "memory")
#define CP_COMMIT() asm volatile("cp.async.commit_group;" ::: "memory")
#define CP_WAIT(n)  asm volatile("cp.async.wait_group %0;" :: "n"(n) : "memory")

// ---------------- prep kernels ----------------
__global__ void prep_x_kernel(const float* __restrict__ x) {
    size_t i = (size_t)blockIdx.x * blockDim.x + threadIdx.x;
    if (i < (size_t)Bsz * Tsz * Fsz) {
        float v = x[i];
        __nv_bfloat16 hi = __float2bfloat16(v);
        d_xhi[i] = hi;
        d_xlo[i] = __float2bfloat16(v - __bfloat162float(hi));
    }
}

__global__ void prep_w_kernel(const float* __restrict__ Wih, const float* __restrict__ Whh) {
    size_t i = (size_t)blockIdx.x * blockDim.x + threadIdx.x;
    if (i < (size_t)NG * 768) {
        int r = (int)(i / 768), kc = (int)(i % 768);
        int u = r >> 2, g = r & 3;
        int orow = g * Hsz + u;
        if (kc < Hsz) {
            float v = Whh[(size_t)orow * Hsz + kc];
            __nv_bfloat16 hi = __float2bfloat16(v);
            d_whh_hi[(size_t)r * Hsz + kc] = hi;
            d_whh_lo[(size_t)r * Hsz + kc] = __float2bfloat16(v - __bfloat162float(hi));
        } else {
            int kf = kc - Hsz;
            float v = Wih[(size_t)orow * Fsz + kf];
            __nv_bfloat16 hi = __float2bfloat16(v);
            d_wih_hi[(size_t)r * Fsz + kf] = hi;
            d_wih_lo[(size_t)r * Fsz + kf] = __float2bfloat16(v - __bfloat162float(hi));
        }
    }
}

__global__ void prep_bias_kernel(const float* __restrict__ bih, const float* __restrict__ bhh) {
    int r = blockIdx.x * blockDim.x + threadIdx.x;
    if (r < NG) {
        int u = r >> 2, g = r & 3;
        d_bias[r] = bih[g * Hsz + u] + bhh[g * Hsz + u];
    }
}

__global__ void init_state_kernel() {
    int i = blockIdx.x * blockDim.x + threadIdx.x;
    if (i < Bsz * Hsz) {
        __nv_bfloat16 z = __float2bfloat16(0.f);
        d_hhi[0][i] = z; d_hhi[1][i] = z;
        d_hlo[0][i] = z; d_hlo[1][i] = z;
    }
    if (blockIdx.x == 0 && threadIdx.x == 0) { d_bar_cnt = 0; d_bar_gen = 0; }
}

// ---------------- x-projection: gates_x[b*T+t][n] = x . Wih_packed^T ----------------
// Grid (1024, 16): M=131072 rows (b*T+t) x N=2048 packed gates. Tiles 128x128.
// 8 warps, warp tile 32x64 (wm 0..3, wn 0..1), frags 2x4, split-bf16 3 products.
__global__ __launch_bounds__(256, 1)
void xproj_kernel()
{
    extern __shared__ __align__(16) char smem[];
    const int tid = threadIdx.x, wid = tid >> 5;
    const int m0 = blockIdx.x * 128;
    const int n0 = blockIdx.y * 128;
    const int wm = wid & 3, wn = wid >> 2;
    const uint32_t sb = smem_u32(smem);

    wmma::fragment<wmma::accumulator, 16, 16, 16, float> acc[2][4];
    #pragma unroll
    for (int mi = 0; mi < 2; mi++)
        #pragma unroll
        for (int ni = 0; ni < 4; ni++)
            wmma::fill_fragment(acc[mi][ni], 0.f);

    auto issue = [&](int c, int s) {
        int k0 = c * XTK;
        uint32_t base = sb + s * XSTAGE_SZ;
        #pragma unroll
        for (int i2 = 0; i2 < 4; i2++) {
            int idx = tid + i2 * 256;           // 1024 16B-chunks: row 0..127, seg 0..7
            int row = idx >> 3, seg = idx & 7;
            uint32_t so = (uint32_t)(row * LDA_S + seg * 8) * 2;
            size_t ga = (size_t)(m0 + row) * Fsz + k0 + seg * 8;
            size_t gw = (size_t)(n0 + row) * Fsz + k0 + seg * 8;
            CP16(base + XAHI + so, d_xhi + ga);
            CP16(base + XALO + so, d_xlo + ga);
            CP16(base + XWHI + so, d_wih_hi + gw);
            CP16(base + XWLO + so, d_wih_lo + gw);
        }
        CP_COMMIT();
    };

    issue(0, 0);
    #pragma unroll 1
    for (int c = 0; c < 4; c++) {
        int s = c & 1;
        if (c + 1 < 4) { issue(c + 1, s ^ 1); CP_WAIT(1); } else { CP_WAIT(0); }
        __syncthreads();
        const __nv_bfloat16* Ah = (const __nv_bfloat16*)(smem + s * XSTAGE_SZ + XAHI);
        const __nv_bfloat16* Al = (const __nv_bfloat16*)(smem + s * XSTAGE_SZ + XALO);
        const __nv_bfloat16* Wh = (const __nv_bfloat16*)(smem + s * XSTAGE_SZ + XWHI);
        const __nv_bfloat16* Wl = (const __nv_bfloat16*)(smem + s * XSTAGE_SZ + XWLO);
        #pragma unroll
        for (int kk = 0; kk < XTK; kk += 16) {
            wmma::fragment<wmma::matrix_a, 16, 16, 16, __nv_bfloat16, wmma::row_major> ah[2], al[2];
            #pragma unroll
            for (int mi = 0; mi < 2; mi++) {
                int r = (wm * 32 + mi * 16) * LDA_S + kk;
                wmma::load_matrix_sync(ah[mi], Ah + r, LDA_S);
                wmma::load_matrix_sync(al[mi], Al + r, LDA_S);
            }
            #pragma unroll
            for (int ni = 0; ni < 4; ni++) {
                wmma::fragment<wmma::matrix_b, 16, 16, 16, __nv_bfloat16, wmma::col_major> bh, bl;
                int r = (wn * 64 + ni * 16) * LDA_S + kk;
                wmma::load_matrix_sync(bh, Wh + r, LDA_S);
                wmma::load_matrix_sync(bl, Wl + r, LDA_S);
                #pragma unroll
                for (int mi = 0; mi < 2; mi++) {
                    wmma::mma_sync(acc[mi][ni], ah[mi], bh, acc[mi][ni]);
                    wmma::mma_sync(acc[mi][ni], ah[mi], bl, acc[mi][ni]);
                    wmma::mma_sync(acc[mi][ni], al[mi], bh, acc[mi][ni]);
                }
            }
        }
        __syncthreads();
    }

    #pragma unroll
    for (int mi = 0; mi < 2; mi++)
        #pragma unroll
        for (int ni = 0; ni < 4; ni++)
            wmma::store_matrix_sync(
                d_gx + (size_t)(m0 + wm * 32 + mi * 16) * NG + n0 + wn * 64 + ni * 16,
                acc[mi][ni], NG, wmma::mem_row_major);
}

// ---------------- persistent recurrent kernel ----------------
// Grid (4, 32): 128 CTAs, all co-resident (1 CTA/SM). W_hh tile + c tile live in
// SMEM for all 256 steps; per step only the h tile streams via cp.async.
// Hand-rolled grid barrier: valid because the whole grid is resident.
__global__ __launch_bounds__(256, 1)
void lstm_persist()
{
    extern __shared__ __align__(16) char smem[];
    const int tid = threadIdx.x, wid = tid >> 5;
    const int b0 = blockIdx.x * TM;
    const int nb = blockIdx.y;
    const int n0 = nb * TN;
    const int wm = wid & 3, wn = wid >> 2;       // warp tile 32x32
    const uint32_t sb = smem_u32(smem);

    // resident W_hh tile (hi+lo), one commit group
    #pragma unroll 4
    for (int i = tid; i < 64 * 64; i += 256) {   // 4096 16B-chunks per buffer
        int row = i >> 6, seg = i & 63;
        uint32_t so = (uint32_t)(row * LDW + seg * 8) * 2;
        size_t g = (size_t)(n0 + row) * Hsz + seg * 8;
        CP16(sb + WHI_OFF + so, d_whh_hi + g);
        CP16(sb + WLO_OFF + so, d_whh_lo + g);
    }
    CP_COMMIT();

    // c tile in SMEM, zero-init
    float* ct = (float*)(smem + CT_OFF);
    for (int i = tid; i < TM * 16; i += 256) ct[i] = 0.f;

    const __nv_bfloat16* Wh = (const __nv_bfloat16*)(smem + WHI_OFF);
    const __nv_bfloat16* Wl = (const __nv_bfloat16*)(smem + WLO_OFF);
    float* G = (float*)(smem + STAGE0_OFF);      // aliases A stages (dead at epilogue)

    #pragma unroll 1
    for (int t = 0; t < Tsz; t++) {
        const __nv_bfloat16* __restrict__ hin_hi = d_hhi[t & 1];
        const __nv_bfloat16* __restrict__ hin_lo = d_hlo[t & 1];

        auto issueA = [&](int c, int s) {
            int k0 = c * TK;
            uint32_t base = sb + STAGE0_OFF + s * STAGE_SZ;
            #pragma unroll
            for (int i2 = 0; i2 < 4; i2++) {
                int idx = tid + i2 * 256;        // 1024 chunks: row 0..127, seg 0..7
                int row = idx >> 3, seg = idx & 7;
                uint32_t so = (uint32_t)(row * LDA_S + seg * 8) * 2;
                size_t g = (size_t)(b0 + row) * Hsz + k0 + seg * 8;
                CP16(base + AHI_OFF + so, hin_hi + g);
                CP16(base + ALO_OFF + so, hin_lo + g);
            }
            CP_COMMIT();
        };

        wmma::fragment<wmma::accumulator, 16, 16, 16, float> acc[2][2];
        #pragma unroll
        for (int mi = 0; mi < 2; mi++)
            #pragma unroll
            for (int ni = 0; ni < 2; ni++)
                wmma::fill_fragment(acc[mi][ni], 0.f);

        issueA(0, 0);
        #pragma unroll 1
        for (int c = 0; c < 8; c++) {
            int s = c & 1;
            if (c + 1 < 8) { issueA(c + 1, s ^ 1); CP_WAIT(1); } else { CP_WAIT(0); }
            __syncthreads();
            const __nv_bfloat16* Ah = (const __nv_bfloat16*)(smem + STAGE0_OFF + s * STAGE_SZ + AHI_OFF);
            const __nv_bfloat16* Al = (const __nv_bfloat16*)(smem + STAGE0_OFF + s * STAGE_SZ + ALO_OFF);
            #pragma unroll
            for (int kk = 0; kk < TK; kk += 16) {
                wmma::fragment<wmma::matrix_a, 16, 16, 16, __nv_bfloat16, wmma::row_major> ah[2], al[2];
                wmma::fragment<wmma::matrix_b, 16, 16, 16, __nv_bfloat16, wmma::col_major> bh[2], bl[2];
                #pragma unroll
                for (int mi = 0; mi < 2; mi++) {
                    int r = (wm * 32 + mi * 16) * LDA_S + kk;
                    wmma::load_matrix_sync(ah[mi], Ah + r, LDA_S);
                    wmma::load_matrix_sync(al[mi], Al + r, LDA_S);
                }
                #pragma unroll
                for (int ni = 0; ni < 2; ni++) {
                    int r = (wn * 32 + ni * 16) * LDW + c * TK + kk;
                    wmma::load_matrix_sync(bh[ni], Wh + r, LDW);
                    wmma::load_matrix_sync(bl[ni], Wl + r, LDW);
                }
                #pragma unroll
                for (int mi = 0; mi < 2; mi++)
                    #pragma unroll
                    for (int ni = 0; ni < 2; ni++) {
                        wmma::mma_sync(acc[mi][ni], ah[mi], bh[ni], acc[mi][ni]);
                        wmma::mma_sync(acc[mi][ni], ah[mi], bl[ni], acc[mi][ni]);
                        wmma::mma_sync(acc[mi][ni], al[mi], bh[ni], acc[mi][ni]);
                    }
            }
            __syncthreads();
        }

        // gate stage (aliases A stages, now dead)
        #pragma unroll
        for (int mi = 0; mi < 2; mi++)
            #pragma unroll
            for (int ni = 0; ni < 2; ni++)
                wmma::store_matrix_sync(G + (wm * 32 + mi * 16) * LDG_S + wn * 32 + ni * 16,
                                        acc[mi][ni], LDG_S, wmma::mem_row_major);
        __syncthreads();

        // epilogue: 2 threads per batch row, 8 units each
        {
            int row = tid >> 1;
            int b = b0 + row;
            __nv_bfloat16* hh = d_hhi[(t + 1) & 1] + (size_t)b * Hsz;
            __nv_bfloat16* hl = d_hlo[(t + 1) & 1] + (size_t)b * Hsz;
            const float* gxr = d_gx + ((size_t)b * Tsz + t) * NG + n0;
            #pragma unroll
            for (int j = 0; j < 8; j++) {
                int ul = (tid & 1) * 8 + j;      // local unit 0..15
                int col = ul * 4;
                float4 g4 = *(const float4*)&G[row * LDG_S + col];
                float4 gx = *(const float4*)(gxr + col);
                float4 bs = *(const float4*)(d_bias + n0 + col);
                float gi = g4.x + gx.x + bs.x;
                float gf = g4.y + gx.y + bs.y;
                float gg = g4.z + gx.z + bs.z;
                float go = g4.w + gx.w + bs.w;
                float iv = 1.f / (1.f + __expf(-gi));
                float fv = 1.f / (1.f + __expf(-gf));
                float gv = 2.f / (1.f + __expf(-2.f * gg)) - 1.f;
                float ov = 1.f / (1.f + __expf(-go));
                float cn = fv * ct[row * 16 + ul] + iv * gv;
                ct[row * 16 + ul] = cn;
                float hn = ov * (2.f / (1.f + __expf(-2.f * cn)) - 1.f);
                __nv_bfloat16 hi = __float2bfloat16(hn);
                int u = nb * 16 + ul;
                hh[u] = hi;
                hl[u] = __float2bfloat16(hn - __bfloat162float(hi));
            }
        }

        // grid barrier (all 128 CTAs resident; reset each launch by init_state_kernel)
        __threadfence();
        __syncthreads();
        if (tid == 0) {
            unsigned target = (unsigned)(t + 1);
            unsigned old = atomicAdd(&d_bar_cnt, 1);
            if (old == NCTA - 1) {
                d_bar_cnt = 0;
                __threadfence();
                d_bar_gen = target;
            } else {
                while (d_bar_gen < target) __nanosleep(32);
            }
            __threadfence();
        }
        __syncthreads();
    }
}

// out[b] = (h_hi+h_lo)[b,:] . W_out[0,:] + b_out[0]
__global__ void head_kernel(const float* __restrict__ Wout,
                            const float* __restrict__ bout,
                            float* __restrict__ out)
{
    int w = (blockIdx.x * blockDim.x + threadIdx.x) >> 5;
    int lane = threadIdx.x & 31;
    if (w >= Bsz) return;
    const __nv_bfloat16* hh = d_hhi[0] + (size_t)w * Hsz;  // T=256 even -> buf 0
    const __nv_bfloat16* hl = d_hlo[0] + (size_t)w * Hsz;
    float s = 0.f;
    for (int k = lane; k < Hsz; k += 32)
        s += (__bfloat162float(hh[k]) + __bfloat162float(hl[k])) * Wout[k];
    #pragma unroll
    for (int o = 16; o > 0; o >>= 1) s += __shfl_xor_sync(0xffffffffu, s, o);
    if (lane == 0) out[w] = s + bout[0];
}

extern "C" void kernel_launch(void* const* d_in, const int* in_sizes, int n_in,
                              void* d_out, int out_size)
{
    const float* x    = (const float*)d_in[0];
    const float* Wih  = (const float*)d_in[1];
    const float* Whh  = (const float*)d_in[2];
    const float* bih  = (const float*)d_in[3];
    const float* bhh  = (const float*)d_in[4];
    const float* Wout = (const float*)d_in[5];
    const float* bout = (const float*)d_in[6];
    float* out = (float*)d_out;
    (void)in_sizes; (void)n_in; (void)out_size;

    cudaFuncSetAttribute(xproj_kernel, cudaFuncAttributeMaxDynamicSharedMemorySize, SMEM_XPROJ);
    cudaFuncSetAttribute(lstm_persist, cudaFuncAttributeMaxDynamicSharedMemorySize, SMEM_STEP);

    size_t nx = (size_t)Bsz * Tsz * Fsz;
    prep_x_kernel<<<(unsigned)((nx + 255) / 256), 256>>>(x);
    prep_w_kernel<<<(NG * 768 + 255) / 256, 256>>>(Wih, Whh);
    prep_bias_kernel<<<(NG + 255) / 256, 256>>>(bih, bhh);
    init_state_kernel<<<(Bsz * Hsz + 255) / 256, 256>>>();

    dim3 xgrid(Bsz * Tsz / 128, NG / 128);   // 1024 x 16
    xproj_kernel<<<xgrid, 256, SMEM_XPROJ>>>();

    dim3 pgrid(Bsz / TM, NG / TN);           // 4 x 32 = 128 CTAs, all resident
    lstm_persist<<<pgrid, 256, SMEM_STEP>>>();

    head_kernel<<<64, 256>>>(Wout, bout, out);
}

// round 8
// speedup vs baseline: 3.7010x; 1.6313x over previous
#include <cuda_runtime.h>
#include <cuda_fp16.h>
#include <mma.h>
#include <cstdint>

using namespace nvcuda;

#define Bsz 512
#define Tsz 256
#define Fsz 256
#define Hsz 512
#define NG  2048            // 4H packed gate rows, r = u*4 + gate
#define NCTA 128            // persistent grid (4 x 32)

// ---- persistent step kernel tiles ----
#define TM 128              // batch tile
#define TN 64               // packed-gate tile (= 16 units)
#define TK 64               // K chunk of the h-GEMM (K=512 -> 8 chunks)
#define LDA_S 72            // A stage ld (fp16)
#define LDW  520            // resident W ld (fp16)
#define LDG_S 68            // gate stage ld (f32)

// step-kernel SMEM layout (bytes)
#define WHI_OFF   0                       // 64 x 520 fp16 = 66560
#define WLO_OFF   66560
#define STAGE0_OFF 133120                 // 2 stages x 18432 (A fp16 only)
#define STAGE_SZ  18432
#define CT_OFF    169984                  // c tile 128 x 16 f32 = 8192
#define SMEM_STEP 178176
// G (f32 gates, 128 x 68 x 4 = 34816) aliases the two A stages (36864 B)

// ---- xproj kernel tiles ----
#define XTK 64
#define XSTAGE_SZ 55296                   // A + Whi + Wlo, each 128x72 fp16
#define XA   0
#define XWHI 18432
#define XWLO 36864
#define SMEM_XPROJ 110592                 // 2 stages; 2 CTAs/SM

// ---------------- device scratch (no runtime allocation) ----------------
__device__ __half d_x16[(size_t)Bsz * Tsz * Fsz];
__device__ __half d_whh_hi[NG * Hsz];
__device__ __half d_whh_lo[NG * Hsz];
__device__ __half d_wih_hi[NG * Fsz];
__device__ __half d_wih_lo[NG * Fsz];
__device__ float  d_bias[NG];
__device__ __half d_h[2][Bsz * Hsz];
__device__ float  d_gx[(size_t)Bsz * Tsz * NG];   // precomputed x-projection
__device__ unsigned          d_bar_cnt;
__device__ volatile unsigned d_bar_gen;

// ---------------- helpers ----------------
__device__ __forceinline__ uint32_t smem_u32(const void* p) {
    uint32_t a;
    asm("{ .reg .u64 t; cvta.to.shared.u64 t, %1; cvt.u32.u64 %0, t; }" : "=r"(a) : "l"(p));
    return a;
}
#define CP16(smaddr, gptr) \
    asm volatile("cp.async.cg.shared.global [%0], [%1], 16;" :: "r"(smaddr), "l"(gptr) : "memory")
#define CP_COMMIT() asm volatile("cp.async.commit_group;" ::: "memory")
#define CP_WAIT(n)  asm volatile("cp.async.wait_group %0;" :: "n"(n) : "memory")

// ---------------- prep kernels ----------------
__global__ void prep_x_kernel(const float* __restrict__ x) {
    size_t i = (size_t)blockIdx.x * blockDim.x + threadIdx.x;
    if (i < (size_t)Bsz * Tsz * Fsz)
        d_x16[i] = __float2half_rn(x[i]);
}

__global__ void prep_w_kernel(const float* __restrict__ Wih, const float* __restrict__ Whh) {
    size_t i = (size_t)blockIdx.x * blockDim.x + threadIdx.x;
    if (i < (size_t)NG * 768) {
        int r = (int)(i / 768), kc = (int)(i % 768);
        int u = r >> 2, g = r & 3;
        int orow = g * Hsz + u;
        if (kc < Hsz) {
            float v = Whh[(size_t)orow * Hsz + kc];
            __half hi = __float2half_rn(v);
            d_whh_hi[(size_t)r * Hsz + kc] = hi;
            d_whh_lo[(size_t)r * Hsz + kc] = __float2half_rn(v - __half2float(hi));
        } else {
            int kf = kc - Hsz;
            float v = Wih[(size_t)orow * Fsz + kf];
            __half hi = __float2half_rn(v);
            d_wih_hi[(size_t)r * Fsz + kf] = hi;
            d_wih_lo[(size_t)r * Fsz + kf] = __float2half_rn(v - __half2float(hi));
        }
    }
}

__global__ void prep_bias_kernel(const float* __restrict__ bih, const float* __restrict__ bhh) {
    int r = blockIdx.x * blockDim.x + threadIdx.x;
    if (r < NG) {
        int u = r >> 2, g = r & 3;
        d_bias[r] = bih[g * Hsz + u] + bhh[g * Hsz + u];
    }
}

__global__ void init_state_kernel() {
    int i = blockIdx.x * blockDim.x + threadIdx.x;
    if (i < Bsz * Hsz) {
        __half z = __float2half_rn(0.f);
        d_h[0][i] = z; d_h[1][i] = z;
    }
    if (blockIdx.x == 0 && threadIdx.x == 0) { d_bar_cnt = 0; d_bar_gen = 0; }
}

// ---------------- x-projection: gx[b*T+t][n] = x_fp16 . (Wih_hi + Wih_lo)^T ----------------
// Grid (1024, 16), 2 CTAs/SM. Warp tile 32x64 (wm 0..3, wn 0..1), 2 fp16 products.
__global__ __launch_bounds__(256, 2)
void xproj_kernel()
{
    extern __shared__ __align__(16) char smem[];
    const int tid = threadIdx.x, wid = tid >> 5;
    const int m0 = blockIdx.x * 128;
    const int n0 = blockIdx.y * 128;
    const int wm = wid & 3, wn = wid >> 2;
    const uint32_t sb = smem_u32(smem);

    wmma::fragment<wmma::accumulator, 16, 16, 16, float> acc[2][4];
    #pragma unroll
    for (int mi = 0; mi < 2; mi++)
        #pragma unroll
        for (int ni = 0; ni < 4; ni++)
            wmma::fill_fragment(acc[mi][ni], 0.f);

    auto issue = [&](int c, int s) {
        int k0 = c * XTK;
        uint32_t base = sb + s * XSTAGE_SZ;
        #pragma unroll
        for (int i2 = 0; i2 < 4; i2++) {
            int idx = tid + i2 * 256;           // 1024 16B-chunks: row 0..127, seg 0..7
            int row = idx >> 3, seg = idx & 7;
            uint32_t so = (uint32_t)(row * LDA_S + seg * 8) * 2;
            size_t ga = (size_t)(m0 + row) * Fsz + k0 + seg * 8;
            size_t gw = (size_t)(n0 + row) * Fsz + k0 + seg * 8;
            CP16(base + XA + so,   d_x16 + ga);
            CP16(base + XWHI + so, d_wih_hi + gw);
            CP16(base + XWLO + so, d_wih_lo + gw);
        }
        CP_COMMIT();
    };

    issue(0, 0);
    #pragma unroll 1
    for (int c = 0; c < 4; c++) {
        int s = c & 1;
        if (c + 1 < 4) { issue(c + 1, s ^ 1); CP_WAIT(1); } else { CP_WAIT(0); }
        __syncthreads();
        const __half* Ax = (const __half*)(smem + s * XSTAGE_SZ + XA);
        const __half* Wh = (const __half*)(smem + s * XSTAGE_SZ + XWHI);
        const __half* Wl = (const __half*)(smem + s * XSTAGE_SZ + XWLO);
        #pragma unroll
        for (int kk = 0; kk < XTK; kk += 16) {
            wmma::fragment<wmma::matrix_a, 16, 16, 16, __half, wmma::row_major> ah[2];
            #pragma unroll
            for (int mi = 0; mi < 2; mi++)
                wmma::load_matrix_sync(ah[mi], Ax + (wm * 32 + mi * 16) * LDA_S + kk, LDA_S);
            #pragma unroll
            for (int ni = 0; ni < 4; ni++) {
                wmma::fragment<wmma::matrix_b, 16, 16, 16, __half, wmma::col_major> bh, bl;
                int r = (wn * 64 + ni * 16) * LDA_S + kk;
                wmma::load_matrix_sync(bh, Wh + r, LDA_S);
                wmma::load_matrix_sync(bl, Wl + r, LDA_S);
                #pragma unroll
                for (int mi = 0; mi < 2; mi++) {
                    wmma::mma_sync(acc[mi][ni], ah[mi], bh, acc[mi][ni]);
                    wmma::mma_sync(acc[mi][ni], ah[mi], bl, acc[mi][ni]);
                }
            }
        }
        __syncthreads();
    }

    #pragma unroll
    for (int mi = 0; mi < 2; mi++)
        #pragma unroll
        for (int ni = 0; ni < 4; ni++)
            wmma::store_matrix_sync(
                d_gx + (size_t)(m0 + wm * 32 + mi * 16) * NG + n0 + wn * 64 + ni * 16,
                acc[mi][ni], NG, wmma::mem_row_major);
}

// ---------------- persistent recurrent kernel ----------------
// Grid (4, 32): 128 co-resident CTAs (1/SM). W_hh fp16 hi+lo tile + c tile live in
// SMEM for all 256 steps; per step only the h fp16 tile streams. 2 fp16 products.
__global__ __launch_bounds__(256, 1)
void lstm_persist()
{
    extern __shared__ __align__(16) char smem[];
    const int tid = threadIdx.x, wid = tid >> 5;
    const int b0 = blockIdx.x * TM;
    const int nb = blockIdx.y;
    const int n0 = nb * TN;
    const int wm = wid & 3, wn = wid >> 2;       // warp tile 32x32
    const uint32_t sb = smem_u32(smem);

    // resident W_hh tile (hi+lo), one commit group
    #pragma unroll 4
    for (int i = tid; i < 64 * 64; i += 256) {   // 4096 16B-chunks per buffer
        int row = i >> 6, seg = i & 63;
        uint32_t so = (uint32_t)(row * LDW + seg * 8) * 2;
        size_t g = (size_t)(n0 + row) * Hsz + seg * 8;
        CP16(sb + WHI_OFF + so, d_whh_hi + g);
        CP16(sb + WLO_OFF + so, d_whh_lo + g);
    }
    CP_COMMIT();

    // c tile in SMEM, zero-init each launch (deterministic under graph replay)
    float* ct = (float*)(smem + CT_OFF);
    for (int i = tid; i < TM * 16; i += 256) ct[i] = 0.f;

    const __half* Wh = (const __half*)(smem + WHI_OFF);
    const __half* Wl = (const __half*)(smem + WLO_OFF);
    float* G = (float*)(smem + STAGE0_OFF);      // aliases A stages (dead at epilogue)

    #pragma unroll 1
    for (int t = 0; t < Tsz; t++) {
        const __half* __restrict__ hin = d_h[t & 1];

        auto issueA = [&](int c, int s) {
            int k0 = c * TK;
            uint32_t base = sb + STAGE0_OFF + s * STAGE_SZ;
            #pragma unroll
            for (int i2 = 0; i2 < 4; i2++) {
                int idx = tid + i2 * 256;        // 1024 chunks: row 0..127, seg 0..7
                int row = idx >> 3, seg = idx & 7;
                uint32_t so = (uint32_t)(row * LDA_S + seg * 8) * 2;
                size_t g = (size_t)(b0 + row) * Hsz + k0 + seg * 8;
                CP16(base + so, hin + g);
            }
            CP_COMMIT();
        };

        wmma::fragment<wmma::accumulator, 16, 16, 16, float> acc[2][2];
        #pragma unroll
        for (int mi = 0; mi < 2; mi++)
            #pragma unroll
            for (int ni = 0; ni < 2; ni++)
                wmma::fill_fragment(acc[mi][ni], 0.f);

        issueA(0, 0);
        #pragma unroll 1
        for (int c = 0; c < 8; c++) {
            int s = c & 1;
            if (c + 1 < 8) { issueA(c + 1, s ^ 1); CP_WAIT(1); } else { CP_WAIT(0); }
            __syncthreads();
            const __half* Ax = (const __half*)(smem + STAGE0_OFF + s * STAGE_SZ);
            #pragma unroll
            for (int kk = 0; kk < TK; kk += 16) {
                wmma::fragment<wmma::matrix_a, 16, 16, 16, __half, wmma::row_major> ah[2];
                wmma::fragment<wmma::matrix_b, 16, 16, 16, __half, wmma::col_major> bh[2], bl[2];
                #pragma unroll
                for (int mi = 0; mi < 2; mi++)
                    wmma::load_matrix_sync(ah[mi], Ax + (wm * 32 + mi * 16) * LDA_S + kk, LDA_S);
                #pragma unroll
                for (int ni = 0; ni < 2; ni++) {
                    int r = (wn * 32 + ni * 16) * LDW + c * TK + kk;
                    wmma::load_matrix_sync(bh[ni], Wh + r, LDW);
                    wmma::load_matrix_sync(bl[ni], Wl + r, LDW);
                }
                #pragma unroll
                for (int mi = 0; mi < 2; mi++)
                    #pragma unroll
                    for (int ni = 0; ni < 2; ni++) {
                        wmma::mma_sync(acc[mi][ni], ah[mi], bh[ni], acc[mi][ni]);
                        wmma::mma_sync(acc[mi][ni], ah[mi], bl[ni], acc[mi][ni]);
                    }
            }
            __syncthreads();
        }

        // gate stage (aliases A stages, now dead)
        #pragma unroll
        for (int mi = 0; mi < 2; mi++)
            #pragma unroll
            for (int ni = 0; ni < 2; ni++)
                wmma::store_matrix_sync(G + (wm * 32 + mi * 16) * LDG_S + wn * 32 + ni * 16,
                                        acc[mi][ni], LDG_S, wmma::mem_row_major);
        __syncthreads();

        // epilogue: 2 threads per batch row, 8 units each
        {
            int row = tid >> 1;
            int b = b0 + row;
            __half* hh = d_h[(t + 1) & 1] + (size_t)b * Hsz;
            const float* gxr = d_gx + ((size_t)b * Tsz + t) * NG + n0;
            #pragma unroll
            for (int j = 0; j < 8; j++) {
                int ul = (tid & 1) * 8 + j;      // local unit 0..15
                int col = ul * 4;
                float4 g4 = *(const float4*)&G[row * LDG_S + col];
                float4 gx = *(const float4*)(gxr + col);
                float4 bs = *(const float4*)(d_bias + n0 + col);
                float gi = g4.x + gx.x + bs.x;
                float gf = g4.y + gx.y + bs.y;
                float gg = g4.z + gx.z + bs.z;
                float go = g4.w + gx.w + bs.w;
                float iv = 1.f / (1.f + __expf(-gi));
                float fv = 1.f / (1.f + __expf(-gf));
                float gv = 2.f / (1.f + __expf(-2.f * gg)) - 1.f;
                float ov = 1.f / (1.f + __expf(-go));
                float cn = fv * ct[row * 16 + ul] + iv * gv;
                ct[row * 16 + ul] = cn;
                float hn = ov * (2.f / (1.f + __expf(-2.f * cn)) - 1.f);
                hh[nb * 16 + ul] = __float2half_rn(hn);
            }
        }

        // grid barrier (all 128 CTAs resident; counters reset by init_state_kernel)
        __threadfence();
        __syncthreads();
        if (tid == 0) {
            unsigned target = (unsigned)(t + 1);
            unsigned old = atomicAdd(&d_bar_cnt, 1);
            if (old == NCTA - 1) {
                d_bar_cnt = 0;
                __threadfence();
                d_bar_gen = target;
            } else {
                while (d_bar_gen < target) __nanosleep(32);
            }
            __threadfence();
        }
        __syncthreads();
    }
}

// out[b] = h_final[b,:] . W_out[0,:] + b_out[0]
__global__ void head_kernel(const float* __restrict__ Wout,
                            const float* __restrict__ bout,
                            float* __restrict__ out)
{
    int w = (blockIdx.x * blockDim.x + threadIdx.x) >> 5;
    int lane = threadIdx.x & 31;
    if (w >= Bsz) return;
    const __half* hr = d_h[0] + (size_t)w * Hsz;  // T=256 even -> buf 0
    float s = 0.f;
    for (int k = lane; k < Hsz; k += 32)
        s += __half2float(hr[k]) * Wout[k];
    #pragma unroll
    for (int o = 16; o > 0; o >>= 1) s += __shfl_xor_sync(0xffffffffu, s, o);
    if (lane == 0) out[w] = s + bout[0];
}

extern "C" void kernel_launch(void* const* d_in, const int* in_sizes, int n_in,
                              void* d_out, int out_size)
{
    const float* x    = (const float*)d_in[0];
    const float* Wih  = (const float*)d_in[1];
    const float* Whh  = (const float*)d_in[2];
    const float* bih  = (const float*)d_in[3];
    const float* bhh  = (const float*)d_in[4];
    const float* Wout = (const float*)d_in[5];
    const float* bout = (const float*)d_in[6];
    float* out = (float*)d_out;
    (void)in_sizes; (void)n_in; (void)out_size;

    cudaFuncSetAttribute(xproj_kernel, cudaFuncAttributeMaxDynamicSharedMemorySize, SMEM_XPROJ);
    cudaFuncSetAttribute(lstm_persist, cudaFuncAttributeMaxDynamicSharedMemorySize, SMEM_STEP);

    size_t nx = (size_t)Bsz * Tsz * Fsz;
    prep_x_kernel<<<(unsigned)((nx + 255) / 256), 256>>>(x);
    prep_w_kernel<<<(NG * 768 + 255) / 256, 256>>>(Wih, Whh);
    prep_bias_kernel<<<(NG + 255) / 256, 256>>>(bih, bhh);
    init_state_kernel<<<(Bsz * Hsz + 255) / 256, 256>>>();

    dim3 xgrid(Bsz * Tsz / 128, NG / 128);   // 1024 x 16
    xproj_kernel<<<xgrid, 256, SMEM_XPROJ>>>();

    dim3 pgrid(Bsz / TM, NG / TN);           // 4 x 32 = 128 CTAs, all resident
    lstm_persist<<<pgrid, 256, SMEM_STEP>>>();

    head_kernel<<<64, 256>>>(Wout, bout, out);
}

// round 9
// speedup vs baseline: 4.1613x; 1.1244x over previous
#include <cuda_runtime.h>
#include <cuda_fp16.h>
#include <mma.h>
#include <cstdint>

using namespace nvcuda;

#define Bsz 512
#define Tsz 256
#define Fsz 256
#define Hsz 512
#define NG  2048            // 4H packed gate rows, r = u*4 + gate
#define NCTA 128            // persistent grid (4 x 32)

// ---- persistent step kernel tiles ----
#define TM 128              // batch tile
#define TN 64               // packed-gate tile (= 16 units)
#define TK 64               // K chunk of the h-GEMM (K=512 -> 8 chunks)
#define LDA_S 72            // A stage ld (fp16)
#define LDW  520            // resident W ld (fp16)
#define LDG_S 68            // gate / gx stage ld (f32)

// step-kernel SMEM layout (bytes)
#define WHI_OFF   0                       // 64 x 520 fp16 = 66560
#define WLO_OFF   66560
#define STAGE0_OFF 133120                 // 3 stages x 18432 (A fp16)
#define STAGE_SZ  18432
#define GX_OFF    188416                  // gx tile 128 x 68 f32 = 34816
#define CT_OFF    223232                  // c tile 128 x 16 f32 = 8192
#define SMEM_STEP 231424
// G (f32 gates, 128 x 68 x 4 = 34816) aliases the A stages (55296 B)

// ---- xproj kernel tiles (single product) ----
#define XTK 64
#define XSTAGE_SZ 36864                   // A + Whi, each 128x72 fp16
#define XA   0
#define XWHI 18432
#define SMEM_XPROJ 73728                  // 2 stages; 2 CTAs/SM

// ---------------- device scratch (no runtime allocation) ----------------
__device__ __half d_x16[(size_t)Bsz * Tsz * Fsz];
__device__ __half d_whh_hi[NG * Hsz];
__device__ __half d_whh_lo[NG * Hsz];
__device__ __half d_wih_hi[NG * Fsz];
__device__ float  d_bias[NG];
__device__ __half d_h[2][Bsz * Hsz];
__device__ float  d_gx[(size_t)Bsz * Tsz * NG];   // precomputed x-projection
__device__ unsigned          d_bar_cnt;
__device__ volatile unsigned d_bar_gen;

// ---------------- helpers ----------------
__device__ __forceinline__ uint32_t smem_u32(const void* p) {
    uint32_t a;
    asm("{ .reg .u64 t; cvta.to.shared.u64 t, %1; cvt.u32.u64 %0, t; }" : "=r"(a) : "l"(p));
    return a;
}
#define CP16(smaddr, gptr) \
    asm volatile("cp.async.cg.shared.global [%0], [%1], 16;" :: "r"(smaddr), "l"(gptr) : "memory")
#define CP_COMMIT() asm volatile("cp.async.commit_group;" ::: "memory")
#define CP_WAIT(n)  asm volatile("cp.async.wait_group %0;" :: "n"(n) : "memory")

// ---------------- prep kernels ----------------
__global__ void prep_x_kernel(const float* __restrict__ x) {
    size_t i = (size_t)blockIdx.x * blockDim.x + threadIdx.x;
    if (i < (size_t)Bsz * Tsz * Fsz)
        d_x16[i] = __float2half_rn(x[i]);
}

__global__ void prep_w_kernel(const float* __restrict__ Wih, const float* __restrict__ Whh) {
    size_t i = (size_t)blockIdx.x * blockDim.x + threadIdx.x;
    if (i < (size_t)NG * 768) {
        int r = (int)(i / 768), kc = (int)(i % 768);
        int u = r >> 2, g = r & 3;
        int orow = g * Hsz + u;
        if (kc < Hsz) {
            float v = Whh[(size_t)orow * Hsz + kc];
            __half hi = __float2half_rn(v);
            d_whh_hi[(size_t)r * Hsz + kc] = hi;
            d_whh_lo[(size_t)r * Hsz + kc] = __float2half_rn(v - __half2float(hi));
        } else {
            int kf = kc - Hsz;
            d_wih_hi[(size_t)r * Fsz + kf] = __float2half_rn(Wih[(size_t)orow * Fsz + kf]);
        }
    }
}

__global__ void prep_bias_kernel(const float* __restrict__ bih, const float* __restrict__ bhh) {
    int r = blockIdx.x * blockDim.x + threadIdx.x;
    if (r < NG) {
        int u = r >> 2, g = r & 3;
        d_bias[r] = bih[g * Hsz + u] + bhh[g * Hsz + u];
    }
}

__global__ void init_state_kernel() {
    int i = blockIdx.x * blockDim.x + threadIdx.x;
    if (i < Bsz * Hsz) {
        __half z = __float2half_rn(0.f);
        d_h[0][i] = z; d_h[1][i] = z;
    }
    if (blockIdx.x == 0 && threadIdx.x == 0) { d_bar_cnt = 0; d_bar_gen = 0; }
}

// ---------------- x-projection: gx[b*T+t][n] = x_fp16 . Wih_fp16^T ----------------
// Grid (1024, 16), 2 CTAs/SM. Warp tile 32x64 (wm 0..3, wn 0..1), 1 fp16 product.
__global__ __launch_bounds__(256, 2)
void xproj_kernel()
{
    extern __shared__ __align__(16) char smem[];
    const int tid = threadIdx.x, wid = tid >> 5;
    const int m0 = blockIdx.x * 128;
    const int n0 = blockIdx.y * 128;
    const int wm = wid & 3, wn = wid >> 2;
    const uint32_t sb = smem_u32(smem);

    wmma::fragment<wmma::accumulator, 16, 16, 16, float> acc[2][4];
    #pragma unroll
    for (int mi = 0; mi < 2; mi++)
        #pragma unroll
        for (int ni = 0; ni < 4; ni++)
            wmma::fill_fragment(acc[mi][ni], 0.f);

    auto issue = [&](int c, int s) {
        int k0 = c * XTK;
        uint32_t base = sb + s * XSTAGE_SZ;
        #pragma unroll
        for (int i2 = 0; i2 < 4; i2++) {
            int idx = tid + i2 * 256;           // 1024 16B-chunks: row 0..127, seg 0..7
            int row = idx >> 3, seg = idx & 7;
            uint32_t so = (uint32_t)(row * LDA_S + seg * 8) * 2;
            if (i2 < 2) {                       // A tile: 1024 chunks? no: A=1024, W=1024
                size_t ga = (size_t)(m0 + row) * Fsz + k0 + seg * 8;
                CP16(base + XA + so, d_x16 + ga);
            } else {
                size_t gw = (size_t)(n0 + row) * Fsz + k0 + seg * 8;
                CP16(base + XWHI + so, d_wih_hi + gw);
            }
        }
        CP_COMMIT();
    };
    // NOTE: A tile = 128 rows x 8 segs = 1024 chunks -> i2 in [0,2) covers 512... fix:
    // use 4 iterations with idx over 1024 for A (i2 0..1 -> 512 chunks) is WRONG.
    // Correct mapping below overrides: we re-issue with full coverage.
    (void)issue;

    auto issue2 = [&](int c, int s) {
        int k0 = c * XTK;
        uint32_t base = sb + s * XSTAGE_SZ;
        #pragma unroll
        for (int i2 = 0; i2 < 4; i2++) {
            int idx = tid + i2 * 256;           // 1024 iterations
            int row = idx >> 3, seg = idx & 7;
            uint32_t so = (uint32_t)(row * LDA_S + seg * 8) * 2;
            size_t ga = (size_t)(m0 + row) * Fsz + k0 + seg * 8;
            size_t gw = (size_t)(n0 + row) * Fsz + k0 + seg * 8;
            CP16(base + XA + so, d_x16 + ga);
            CP16(base + XWHI + so, d_wih_hi + gw);
        }
        CP_COMMIT();
    };

    issue2(0, 0);
    #pragma unroll 1
    for (int c = 0; c < 4; c++) {
        int s = c & 1;
        if (c + 1 < 4) { issue2(c + 1, s ^ 1); CP_WAIT(1); } else { CP_WAIT(0); }
        __syncthreads();
        const __half* Ax = (const __half*)(smem + s * XSTAGE_SZ + XA);
        const __half* Wh = (const __half*)(smem + s * XSTAGE_SZ + XWHI);
        #pragma unroll
        for (int kk = 0; kk < XTK; kk += 16) {
            wmma::fragment<wmma::matrix_a, 16, 16, 16, __half, wmma::row_major> ah[2];
            #pragma unroll
            for (int mi = 0; mi < 2; mi++)
                wmma::load_matrix_sync(ah[mi], Ax + (wm * 32 + mi * 16) * LDA_S + kk, LDA_S);
            #pragma unroll
            for (int ni = 0; ni < 4; ni++) {
                wmma::fragment<wmma::matrix_b, 16, 16, 16, __half, wmma::col_major> bh;
                wmma::load_matrix_sync(bh, Wh + (wn * 64 + ni * 16) * LDA_S + kk, LDA_S);
                #pragma unroll
                for (int mi = 0; mi < 2; mi++)
                    wmma::mma_sync(acc[mi][ni], ah[mi], bh, acc[mi][ni]);
            }
        }
        __syncthreads();
    }

    #pragma unroll
    for (int mi = 0; mi < 2; mi++)
        #pragma unroll
        for (int ni = 0; ni < 4; ni++)
            wmma::store_matrix_sync(
                d_gx + (size_t)(m0 + wm * 32 + mi * 16) * NG + n0 + wn * 64 + ni * 16,
                acc[mi][ni], NG, wmma::mem_row_major);
}

// ---------------- persistent recurrent kernel ----------------
// Grid (4, 32): 128 co-resident CTAs (1/SM). W_hh fp16 hi+lo tile + c tile live in
// SMEM for all 256 steps. 3-stage A pipeline, 1 sync/chunk (issue-at-bottom),
// gx tile prefetched into SMEM during the mainloop.
__global__ __launch_bounds__(256, 1)
void lstm_persist()
{
    extern __shared__ __align__(16) char smem[];
    const int tid = threadIdx.x, wid = tid >> 5;
    const int b0 = blockIdx.x * TM;
    const int nb = blockIdx.y;
    const int n0 = nb * TN;
    const int wm = wid & 3, wn = wid >> 2;       // warp tile 32x32
    const uint32_t sb = smem_u32(smem);

    // resident W_hh tile (hi+lo), one commit group (folded into first CP_WAIT)
    #pragma unroll 4
    for (int i = tid; i < 64 * 64; i += 256) {   // 4096 16B-chunks per buffer
        int row = i >> 6, seg = i & 63;
        uint32_t so = (uint32_t)(row * LDW + seg * 8) * 2;
        size_t g = (size_t)(n0 + row) * Hsz + seg * 8;
        CP16(sb + WHI_OFF + so, d_whh_hi + g);
        CP16(sb + WLO_OFF + so, d_whh_lo + g);
    }
    CP_COMMIT();

    // c tile in SMEM, zero-init each launch (deterministic under graph replay)
    float* ct = (float*)(smem + CT_OFF);
    for (int i = tid; i < TM * 16; i += 256) ct[i] = 0.f;

    const __half* Wh = (const __half*)(smem + WHI_OFF);
    const __half* Wl = (const __half*)(smem + WLO_OFF);
    float* G = (float*)(smem + STAGE0_OFF);      // aliases A stages (dead at epilogue)
    const float* gxs = (const float*)(smem + GX_OFF);

    #pragma unroll 1
    for (int t = 0; t < Tsz; t++) {
        const __half* __restrict__ hin = d_h[t & 1];

        auto issueA = [&](int c, int s) {
            int k0 = c * TK;
            uint32_t base = sb + STAGE0_OFF + s * STAGE_SZ;
            #pragma unroll
            for (int i2 = 0; i2 < 4; i2++) {
                int idx = tid + i2 * 256;        // 1024 chunks: row 0..127, seg 0..7
                int row = idx >> 3, seg = idx & 7;
                uint32_t so = (uint32_t)(row * LDA_S + seg * 8) * 2;
                size_t g = (size_t)(b0 + row) * Hsz + k0 + seg * 8;
                CP16(base + so, hin + g);
            }
            CP_COMMIT();
        };
        auto issueGX = [&]() {
            uint32_t base = sb + GX_OFF;
            #pragma unroll
            for (int i2 = 0; i2 < 8; i2++) {
                int idx = tid + i2 * 256;        // 2048 chunks: row 0..127, seg 0..15
                int row = idx >> 4, seg = idx & 15;
                uint32_t so = (uint32_t)(row * LDG_S + seg * 4) * 4;
                const float* g = d_gx + ((size_t)(b0 + row) * Tsz + t) * NG + n0 + seg * 4;
                CP16(base + so, g);
            }
            CP_COMMIT();
        };

        wmma::fragment<wmma::accumulator, 16, 16, 16, float> acc[2][2];
        #pragma unroll
        for (int mi = 0; mi < 2; mi++)
            #pragma unroll
            for (int ni = 0; ni < 2; ni++)
                wmma::fill_fragment(acc[mi][ni], 0.f);

        issueA(0, 0);
        issueA(1, 1);
        #pragma unroll 1
        for (int c = 0; c < 8; c++) {
            // top: need A(c). Newer outstanding: A(c+1) (+GX after c==5) -> wait 1,
            // except c==6 where {A7, GX} are newer -> wait 2.
            if (c == 6) { CP_WAIT(2); } else { CP_WAIT(1); }
            __syncthreads();
            const __half* Ax = (const __half*)(smem + STAGE0_OFF + (c % 3) * STAGE_SZ);
            #pragma unroll
            for (int kk = 0; kk < TK; kk += 16) {
                wmma::fragment<wmma::matrix_a, 16, 16, 16, __half, wmma::row_major> ah[2];
                wmma::fragment<wmma::matrix_b, 16, 16, 16, __half, wmma::col_major> bh[2], bl[2];
                #pragma unroll
                for (int mi = 0; mi < 2; mi++)
                    wmma::load_matrix_sync(ah[mi], Ax + (wm * 32 + mi * 16) * LDA_S + kk, LDA_S);
                #pragma unroll
                for (int ni = 0; ni < 2; ni++) {
                    int r = (wn * 32 + ni * 16) * LDW + c * TK + kk;
                    wmma::load_matrix_sync(bh[ni], Wh + r, LDW);
                    wmma::load_matrix_sync(bl[ni], Wl + r, LDW);
                }
                #pragma unroll
                for (int mi = 0; mi < 2; mi++)
                    #pragma unroll
                    for (int ni = 0; ni < 2; ni++) {
                        wmma::mma_sync(acc[mi][ni], ah[mi], bh[ni], acc[mi][ni]);
                        wmma::mma_sync(acc[mi][ni], ah[mi], bl[ni], acc[mi][ni]);
                    }
            }
            // bottom: prefetch. Safe: every warp passed this iteration's sync, so no
            // straggler is still reading stage (c+2)%3 (last read at iteration c-1).
            if (c + 2 < 8) issueA(c + 2, (c + 2) % 3);
            if (c == 5) issueGX();
        }

        CP_WAIT(0);                              // gx resident
        __syncthreads();                         // all MMA done before G store
        #pragma unroll
        for (int mi = 0; mi < 2; mi++)
            #pragma unroll
            for (int ni = 0; ni < 2; ni++)
                wmma::store_matrix_sync(G + (wm * 32 + mi * 16) * LDG_S + wn * 32 + ni * 16,
                                        acc[mi][ni], LDG_S, wmma::mem_row_major);
        __syncthreads();

        // epilogue: 2 threads per batch row, 8 units each (gx from SMEM)
        {
            int row = tid >> 1;
            int b = b0 + row;
            __half* hh = d_h[(t + 1) & 1] + (size_t)b * Hsz;
            #pragma unroll
            for (int j = 0; j < 8; j++) {
                int ul = (tid & 1) * 8 + j;      // local unit 0..15
                int col = ul * 4;
                float4 g4 = *(const float4*)&G[row * LDG_S + col];
                float4 gx = *(const float4*)&gxs[row * LDG_S + col];
                float4 bs = *(const float4*)(d_bias + n0 + col);
                float gi = g4.x + gx.x + bs.x;
                float gf = g4.y + gx.y + bs.y;
                float gg = g4.z + gx.z + bs.z;
                float go = g4.w + gx.w + bs.w;
                float iv = 1.f / (1.f + __expf(-gi));
                float fv = 1.f / (1.f + __expf(-gf));
                float gv = 2.f / (1.f + __expf(-2.f * gg)) - 1.f;
                float ov = 1.f / (1.f + __expf(-go));
                float cn = fv * ct[row * 16 + ul] + iv * gv;
                ct[row * 16 + ul] = cn;
                float hn = ov * (2.f / (1.f + __expf(-2.f * cn)) - 1.f);
                hh[nb * 16 + ul] = __float2half_rn(hn);
            }
        }

        // grid barrier (all 128 CTAs resident; counters reset by init_state_kernel)
        __threadfence();
        __syncthreads();
        if (tid == 0) {
            unsigned target = (unsigned)(t + 1);
            unsigned old = atomicAdd(&d_bar_cnt, 1);
            if (old == NCTA - 1) {
                d_bar_cnt = 0;
                __threadfence();
                d_bar_gen = target;
            } else {
                while (d_bar_gen < target) __nanosleep(32);
            }
            __threadfence();
        }
        __syncthreads();
    }
}

// out[b] = h_final[b,:] . W_out[0,:] + b_out[0]
__global__ void head_kernel(const float* __restrict__ Wout,
                            const float* __restrict__ bout,
                            float* __restrict__ out)
{
    int w = (blockIdx.x * blockDim.x + threadIdx.x) >> 5;
    int lane = threadIdx.x & 31;
    if (w >= Bsz) return;
    const __half* hr = d_h[0] + (size_t)w * Hsz;  // T=256 even -> buf 0
    float s = 0.f;
    for (int k = lane; k < Hsz; k += 32)
        s += __half2float(hr[k]) * Wout[k];
    #pragma unroll
    for (int o = 16; o > 0; o >>= 1) s += __shfl_xor_sync(0xffffffffu, s, o);
    if (lane == 0) out[w] = s + bout[0];
}

extern "C" void kernel_launch(void* const* d_in, const int* in_sizes, int n_in,
                              void* d_out, int out_size)
{
    const float* x    = (const float*)d_in[0];
    const float* Wih  = (const float*)d_in[1];
    const float* Whh  = (const float*)d_in[2];
    const float* bih  = (const float*)d_in[3];
    const float* bhh  = (const float*)d_in[4];
    const float* Wout = (const float*)d_in[5];
    const float* bout = (const float*)d_in[6];
    float* out = (float*)d_out;
    (void)in_sizes; (void)n_in; (void)out_size;

    cudaFuncSetAttribute(xproj_kernel, cudaFuncAttributeMaxDynamicSharedMemorySize, SMEM_XPROJ);
    cudaFuncSetAttribute(lstm_persist, cudaFuncAttributeMaxDynamicSharedMemorySize, SMEM_STEP);

    size_t nx = (size_t)Bsz * Tsz * Fsz;
    prep_x_kernel<<<(unsigned)((nx + 255) / 256), 256>>>(x);
    prep_w_kernel<<<(NG * 768 + 255) / 256, 256>>>(Wih, Whh);
    prep_bias_kernel<<<(NG + 255) / 256, 256>>>(bih, bhh);
    init_state_kernel<<<(Bsz * Hsz + 255) / 256, 256>>>();

    dim3 xgrid(Bsz * Tsz / 128, NG / 128);   // 1024 x 16
    xproj_kernel<<<xgrid, 256, SMEM_XPROJ>>>();

    dim3 pgrid(Bsz / TM, NG / TN);           // 4 x 32 = 128 CTAs, all resident
    lstm_persist<<<pgrid, 256, SMEM_STEP>>>();

    head_kernel<<<64, 256>>>(Wout, bout, out);
}